// round 1
// baseline (speedup 1.0000x reference)
#include <cuda_runtime.h>
#include <math.h>

#define NFFT   4096
#define CCH    512
#define NPIX   784
#define NB     8
#define SLOTS  18
#define DOUT   8705
#define NTHR   512

// Scratch (no cudaMalloc allowed): per-batch accumulated product spectra + first moment.
__device__ float2 g_acc2[NB][NFFT];
__device__ float2 g_acc3[NB][NFFT];
__device__ float  g_first[NB][CCH];

__device__ __forceinline__ float2 cmul(float2 a, float2 b) {
    return make_float2(a.x * b.x - a.y * b.y, a.x * b.y + a.y * b.x);
}

// One Stockham radix-4 DIF stage: src -> dst, natural-order autosort.
// n = 1<<ln (current transform length), s = 1<<ls (stride). s*n == 4096 at every
// stage so the 4 loads are always at t, t+1024, t+2048, t+3072 (conflict-free).
// Twiddle w = e^{-2*pi*i*p/n} = tw[p << (12-ln)]; INV conjugates (inverse DFT).
template<bool INV>
__device__ __forceinline__ void fft_stage(const float2* __restrict__ src,
                                          float2* __restrict__ dst,
                                          const float2* __restrict__ tw,
                                          int ln, int ls, int tid)
{
    #pragma unroll
    for (int t = tid; t < 1024; t += NTHR) {
        int p = t >> ls;
        int q = t & ((1 << ls) - 1);
        float2 a = src[t];
        float2 b = src[t + 1024];
        float2 c = src[t + 2048];
        float2 d = src[t + 3072];
        float2 apc  = make_float2(a.x + c.x, a.y + c.y);
        float2 amc  = make_float2(a.x - c.x, a.y - c.y);
        float2 bpd  = make_float2(b.x + d.x, b.y + d.y);
        float2 jbmd = make_float2(-(b.y - d.y), b.x - d.x);   // i*(b-d)
        float2 y0 = make_float2(apc.x + bpd.x, apc.y + bpd.y);
        float2 y2 = make_float2(apc.x - bpd.x, apc.y - bpd.y);
        float2 y1, y3;
        if (!INV) {
            y1 = make_float2(amc.x - jbmd.x, amc.y - jbmd.y);
            y3 = make_float2(amc.x + jbmd.x, amc.y + jbmd.y);
        } else {
            y1 = make_float2(amc.x + jbmd.x, amc.y + jbmd.y);
            y3 = make_float2(amc.x - jbmd.x, amc.y - jbmd.y);
        }
        int ti = p << (12 - ln);
        float2 w1 = tw[ti], w2 = tw[2 * ti], w3 = tw[3 * ti];
        if (INV) { w1.y = -w1.y; w2.y = -w2.y; w3.y = -w3.y; }
        y1 = cmul(y1, w1);
        y2 = cmul(y2, w2);
        y3 = cmul(y3, w3);
        int o = q + (p << (ls + 2));
        int s = 1 << ls;
        dst[o]         = y0;
        dst[o + s]     = y1;
        dst[o + 2 * s] = y2;
        dst[o + 3 * s] = y3;
    }
}

// 4096-point complex FFT (forward or inverse), A as input, B scratch, result in `out`.
// Stage chain: A->B->A->B->A->B->out. Ends with a __syncthreads().
template<bool INV>
__device__ void fft4096(float2* A, float2* B, float2* out, const float2* tw, int tid)
{
    fft_stage<INV>(A, B, tw, 12, 0,  tid); __syncthreads();
    fft_stage<INV>(B, A, tw, 10, 2,  tid); __syncthreads();
    fft_stage<INV>(A, B, tw,  8, 4,  tid); __syncthreads();
    fft_stage<INV>(B, A, tw,  6, 6,  tid); __syncthreads();
    fft_stage<INV>(A, B, tw,  4, 8,  tid); __syncthreads();
    fft_stage<INV>(B, out, tw, 2, 10, tid); __syncthreads();
}

__global__ void zero_kernel()
{
    int i = blockIdx.x * blockDim.x + threadIdx.x;   // 65536 threads
    float* p2 = (float*)g_acc2;
    float* p3 = (float*)g_acc3;
    p2[i] = 0.f;
    p3[i] = 0.f;
}

__global__ void first_kernel(const float* __restrict__ x)
{
    int b = blockIdx.x;
    int c = threadIdx.x;           // 512 threads
    const float* p = x + (size_t)b * NPIX * CCH + c;
    float s = 0.f;
    #pragma unroll 8
    for (int i = 0; i < NPIX; i++) s += p[(size_t)i * CCH];
    g_first[b][c] = s;             // divided by 784 in finalize
}

__global__ void __launch_bounds__(NTHR, 1)
poly_sketch_kernel(const float* __restrict__ x,
                   const int* __restrict__ h_idx,
                   const int* __restrict__ s_bits)
{
    extern __shared__ float2 smem[];
    float2* tw  = smem;
    float2* A   = smem + NFFT;
    float2* B   = smem + 2 * NFFT;
    float2* F0  = smem + 3 * NFFT;
    float2* ac2 = smem + 4 * NFFT;
    float2* ac3 = smem + 5 * NFFT;
    __shared__ int   hsh[3][CCH];
    __shared__ float sg[3][CCH];

    int tid  = threadIdx.x;
    int b    = blockIdx.x / SLOTS;
    int slot = blockIdx.x % SLOTS;

    for (int j = tid; j < NFFT; j += NTHR) {
        float sn, cs;
        sincospif(-(float)j * (1.0f / 2048.0f), &sn, &cs);  // e^{-2*pi*i*j/4096}
        tw[j]  = make_float2(cs, sn);
        ac2[j] = make_float2(0.f, 0.f);
        ac3[j] = make_float2(0.f, 0.f);
    }
    #pragma unroll
    for (int t = 0; t < 3; t++) {
        hsh[t][tid] = h_idx[t * CCH + tid];
        sg[t][tid]  = (float)(2 * s_bits[t * CCH + tid] - 1);
    }
    __syncthreads();

    for (int pix = slot; pix < NPIX; pix += SLOTS) {
        float xv = x[((size_t)(b * NPIX + pix)) * CCH + tid];

        // ---- order-0 sketch -> FFT -> F0
        for (int i = tid; i < NFFT; i += NTHR) A[i] = make_float2(0.f, 0.f);
        __syncthreads();
        atomicAdd(&A[hsh[0][tid]].x, xv * sg[0][tid]);
        __syncthreads();
        fft4096<false>(A, B, F0, tw, tid);

        // ---- order-1 sketch -> FFT -> A;  P2 = F0*F1, accumulate, keep in F0
        for (int i = tid; i < NFFT; i += NTHR) A[i] = make_float2(0.f, 0.f);
        __syncthreads();
        atomicAdd(&A[hsh[1][tid]].x, xv * sg[1][tid]);
        __syncthreads();
        fft4096<false>(A, B, A, tw, tid);
        for (int i = tid; i < NFFT; i += NTHR) {
            float2 pr = cmul(F0[i], A[i]);
            ac2[i].x += pr.x; ac2[i].y += pr.y;
            F0[i] = pr;
        }
        __syncthreads();

        // ---- order-2 sketch -> FFT -> A;  P3 = P2*F2, accumulate
        for (int i = tid; i < NFFT; i += NTHR) A[i] = make_float2(0.f, 0.f);
        __syncthreads();
        atomicAdd(&A[hsh[2][tid]].x, xv * sg[2][tid]);
        __syncthreads();
        fft4096<false>(A, B, A, tw, tid);
        for (int i = tid; i < NFFT; i += NTHR) {
            float2 pr = cmul(F0[i], A[i]);
            ac3[i].x += pr.x; ac3[i].y += pr.y;
        }
        __syncthreads();
    }

    // flush per-CTA accumulators to the per-batch global accumulators
    for (int i = tid; i < NFFT; i += NTHR) {
        atomicAdd(&g_acc2[b][i].x, ac2[i].x);
        atomicAdd(&g_acc2[b][i].y, ac2[i].y);
        atomicAdd(&g_acc3[b][i].x, ac3[i].x);
        atomicAdd(&g_acc3[b][i].y, ac3[i].y);
    }
}

__global__ void __launch_bounds__(NTHR, 1)
finalize_kernel(const float* __restrict__ alpha, float* __restrict__ out)
{
    extern __shared__ float2 smem[];
    float2* tw  = smem;
    float2* A   = smem + NFFT;
    float2* B   = smem + 2 * NFFT;
    float*  phi = (float*)(smem + 3 * NFFT);   // 8712 floats
    __shared__ float red[17];

    int tid = threadIdx.x;
    int b   = blockIdx.x;

    for (int j = tid; j < NFFT; j += NTHR) {
        float sn, cs;
        sincospif(-(float)j * (1.0f / 2048.0f), &sn, &cs);
        tw[j] = make_float2(cs, sn);
    }
    __syncthreads();

    const float inv_n = 1.0f / ((float)NPIX * (float)NFFT); // ifft 1/N and pixel mean

    // order-2 term
    for (int i = tid; i < NFFT; i += NTHR) A[i] = g_acc2[b][i];
    __syncthreads();
    fft4096<true>(A, B, A, tw, tid);
    {
        float a2 = alpha[2] * inv_n;
        for (int i = tid; i < NFFT; i += NTHR) phi[513 + i] = A[i].x * a2;
    }

    // order-3 term
    for (int i = tid; i < NFFT; i += NTHR) A[i] = g_acc3[b][i];
    __syncthreads();
    fft4096<true>(A, B, A, tw, tid);
    {
        float a3 = alpha[3] * inv_n;
        for (int i = tid; i < NFFT; i += NTHR) phi[513 + NFFT + i] = A[i].x * a3;
    }

    if (tid == 0) phi[0] = alpha[0];
    phi[1 + tid] = alpha[1] * g_first[b][tid] * (1.0f / (float)NPIX);
    __syncthreads();

    // signed sqrt (matching jnp.sign semantics incl. sign(0)=0) + norm reduction
    float lsum = 0.f;
    for (int i = tid; i < DOUT; i += NTHR) {
        float v = phi[i];
        float r;
        if (v > 0.f)      r =  sqrtf(v + 1e-12f);
        else if (v < 0.f) r = -sqrtf(-v + 1e-12f);
        else              r = 0.f;
        phi[i] = r;
        lsum += r * r;
    }
    #pragma unroll
    for (int off = 16; off > 0; off >>= 1)
        lsum += __shfl_down_sync(0xffffffffu, lsum, off);
    if ((tid & 31) == 0) red[tid >> 5] = lsum;
    __syncthreads();
    if (tid == 0) {
        float s = 0.f;
        #pragma unroll
        for (int k = 0; k < 16; k++) s += red[k];
        red[16] = 1.0f / sqrtf(s);
    }
    __syncthreads();
    float rn = red[16];
    for (int i = tid; i < DOUT; i += NTHR)
        out[(size_t)b * DOUT + i] = phi[i] * rn;
}

extern "C" void kernel_launch(void* const* d_in, const int* in_sizes, int n_in,
                              void* d_out, int out_size)
{
    const float* x     = (const float*)d_in[0];
    const float* alpha = (const float*)d_in[1];
    const int*   h     = (const int*)d_in[2];
    const int*   sb    = (const int*)d_in[3];
    float*       out   = (float*)d_out;

    const int MAIN_SMEM = 6 * NFFT * (int)sizeof(float2);               // 196608
    const int FIN_SMEM  = 3 * NFFT * (int)sizeof(float2) + 8712 * 4;    // 133152

    cudaFuncSetAttribute(poly_sketch_kernel,
                         cudaFuncAttributeMaxDynamicSharedMemorySize, MAIN_SMEM);
    cudaFuncSetAttribute(finalize_kernel,
                         cudaFuncAttributeMaxDynamicSharedMemorySize, FIN_SMEM);

    zero_kernel<<<256, 256>>>();
    first_kernel<<<NB, CCH>>>(x);
    poly_sketch_kernel<<<NB * SLOTS, NTHR, MAIN_SMEM>>>(x, h, sb);
    finalize_kernel<<<NB, NTHR, FIN_SMEM>>>(alpha, out);
}

// round 2
// speedup vs baseline: 1.6945x; 1.6945x over previous
#include <cuda_runtime.h>
#include <math.h>

#define NFFT   4096
#define NHALF  2048
#define NSPEC  2049            // Hermitian half-spectrum bins 0..2048
#define CCH    512
#define NPIX   784
#define NB     8
#define SLOTS  18
#define DOUT   8705
#define NTHR   1024            // poly_sketch threads
#define NTHF   512             // finalize threads

// Scratch (no cudaMalloc allowed): per-batch accumulated half product spectra + first moment.
__device__ float2 g_acc2[NB][NSPEC];
__device__ float2 g_acc3[NB][NSPEC];
__device__ float  g_first[NB][CCH];

__device__ __forceinline__ float2 cmul(float2 a, float2 b) {
    return make_float2(a.x * b.x - a.y * b.y, a.x * b.y + a.y * b.x);
}

// One Stockham radix-4 DIF stage, generic transform size (quarter = N/4).
// Twiddle w = e^{-2*pi*i*p/(1<<ln)} looked up in the shared 4096-entry table.
// INV conjugates (inverse DFT, unnormalized).
template<bool INV>
__device__ __forceinline__ void fft_stage_g(const float2* __restrict__ src,
                                            float2* __restrict__ dst,
                                            const float2* __restrict__ tw,
                                            int ln, int ls, int quarter,
                                            int tid, int nt)
{
    for (int t = tid; t < quarter; t += nt) {
        int p = t >> ls;
        int q = t & ((1 << ls) - 1);
        float2 a = src[t];
        float2 b = src[t + quarter];
        float2 c = src[t + 2 * quarter];
        float2 d = src[t + 3 * quarter];
        float2 apc  = make_float2(a.x + c.x, a.y + c.y);
        float2 amc  = make_float2(a.x - c.x, a.y - c.y);
        float2 bpd  = make_float2(b.x + d.x, b.y + d.y);
        float2 jbmd = make_float2(-(b.y - d.y), b.x - d.x);   // i*(b-d)
        float2 y0 = make_float2(apc.x + bpd.x, apc.y + bpd.y);
        float2 y2 = make_float2(apc.x - bpd.x, apc.y - bpd.y);
        float2 y1, y3;
        if (!INV) {
            y1 = make_float2(amc.x - jbmd.x, amc.y - jbmd.y);
            y3 = make_float2(amc.x + jbmd.x, amc.y + jbmd.y);
        } else {
            y1 = make_float2(amc.x + jbmd.x, amc.y + jbmd.y);
            y3 = make_float2(amc.x - jbmd.x, amc.y - jbmd.y);
        }
        int ti = p << (12 - ln);
        float2 w1 = tw[ti], w2 = tw[2 * ti], w3 = tw[3 * ti];
        if (INV) { w1.y = -w1.y; w2.y = -w2.y; w3.y = -w3.y; }
        y1 = cmul(y1, w1);
        y2 = cmul(y2, w2);
        y3 = cmul(y3, w3);
        int o = q + (p << (ls + 2));
        int s = 1 << ls;
        dst[o]         = y0;
        dst[o + s]     = y1;
        dst[o + 2 * s] = y2;
        dst[o + 3 * s] = y3;
    }
}

// 4096-pt complex FFT: chain A->B->A->B->A->B->out (out must differ from B).
template<bool INV>
__device__ void fft4096(float2* A, float2* B, float2* out, const float2* tw,
                        int tid, int nt)
{
    fft_stage_g<INV>(A, B, tw, 12, 0,  1024, tid, nt); __syncthreads();
    fft_stage_g<INV>(B, A, tw, 10, 2,  1024, tid, nt); __syncthreads();
    fft_stage_g<INV>(A, B, tw,  8, 4,  1024, tid, nt); __syncthreads();
    fft_stage_g<INV>(B, A, tw,  6, 6,  1024, tid, nt); __syncthreads();
    fft_stage_g<INV>(A, B, tw,  4, 8,  1024, tid, nt); __syncthreads();
    fft_stage_g<INV>(B, out, tw, 2, 10, 1024, tid, nt); __syncthreads();
}

// 2048-pt complex FFT in-place over X (Y = scratch): 5 radix-4 stages + final
// radix-2. Result lands back in X.
template<bool INV>
__device__ void fft2048(float2* X, float2* Y, const float2* tw, int tid, int nt)
{
    fft_stage_g<INV>(X, Y, tw, 11, 0, 512, tid, nt); __syncthreads();
    fft_stage_g<INV>(Y, X, tw,  9, 2, 512, tid, nt); __syncthreads();
    fft_stage_g<INV>(X, Y, tw,  7, 4, 512, tid, nt); __syncthreads();
    fft_stage_g<INV>(Y, X, tw,  5, 6, 512, tid, nt); __syncthreads();
    fft_stage_g<INV>(X, Y, tw,  3, 8, 512, tid, nt); __syncthreads();
    for (int t = tid; t < 1024; t += nt) {           // radix-2, p==0, no twiddle
        float2 a = Y[t], b = Y[t + 1024];
        X[t]        = make_float2(a.x + b.x, a.y + b.y);
        X[t + 1024] = make_float2(a.x - b.x, a.y - b.y);
    }
    __syncthreads();
}

__global__ void zero_kernel()
{
    int i = blockIdx.x * blockDim.x + threadIdx.x;
    int n = NB * NSPEC * 2;                 // floats per array
    if (i < n) {
        ((float*)g_acc2)[i] = 0.f;
        ((float*)g_acc3)[i] = 0.f;
    }
}

__global__ void first_kernel(const float* __restrict__ x)
{
    int b = blockIdx.x;
    int c = threadIdx.x;           // 512 threads
    const float* p = x + (size_t)b * NPIX * CCH + c;
    float s = 0.f;
    #pragma unroll 8
    for (int i = 0; i < NPIX; i++) s += p[(size_t)i * CCH];
    g_first[b][c] = s;             // divided by 784 in finalize
}

__global__ void __launch_bounds__(NTHR, 1)
poly_sketch_kernel(const float* __restrict__ x,
                   const int* __restrict__ h_idx,
                   const int* __restrict__ s_bits)
{
    extern __shared__ float2 smem[];
    float2* tw  = smem;                    // 4096
    float2* A   = smem + NFFT;             // 4096: packed s0+i*s1 -> Z
    float2* B   = smem + 2 * NFFT;         // 4096: fft scratch; then C(2048)+scratch
    float2* ac2 = smem + 3 * NFFT;         // 2049
    float2* ac3 = ac2 + NSPEC;             // 2049
    __shared__ int   hsh[3][CCH];
    __shared__ float sg[3][CCH];

    int tid  = threadIdx.x;
    int b    = blockIdx.x / SLOTS;
    int slot = blockIdx.x % SLOTS;

    for (int j = tid; j < NFFT; j += NTHR) {
        float sn, cs;
        sincospif(-(float)j * (1.0f / 2048.0f), &sn, &cs);  // e^{-2*pi*i*j/4096}
        tw[j] = make_float2(cs, sn);
    }
    for (int j = tid; j < NSPEC; j += NTHR) {
        ac2[j] = make_float2(0.f, 0.f);
        ac3[j] = make_float2(0.f, 0.f);
    }
    if (tid < CCH) {
        #pragma unroll
        for (int t = 0; t < 3; t++) {
            hsh[t][tid] = h_idx[t * CCH + tid];
            sg[t][tid]  = (float)(2 * s_bits[t * CCH + tid] - 1);
        }
    }
    __syncthreads();

    for (int pix = slot; pix < NPIX; pix += SLOTS) {
        float xv = 0.f;
        if (tid < CCH) xv = x[((size_t)(b * NPIX + pix)) * CCH + tid];

        // ---- pack sketches 0,1 as A = s0 + i*s1, FFT -> Z (in A)
        for (int i = tid; i < 2048; i += NTHR)           // float4 zero of A
            ((float4*)A)[i] = make_float4(0.f, 0.f, 0.f, 0.f);
        __syncthreads();
        if (tid < CCH) {
            atomicAdd(&A[hsh[0][tid]].x, xv * sg[0][tid]);
            atomicAdd(&A[hsh[1][tid]].y, xv * sg[1][tid]);
        }
        __syncthreads();
        fft4096<false>(A, B, A, tw, tid, NTHR);          // Z in A, B free

        // ---- sketch 2 packed into 2048 complex (even+i*odd), FFT in B[0..2047]
        for (int i = tid; i < 1024; i += NTHR)
            ((float4*)B)[i] = make_float4(0.f, 0.f, 0.f, 0.f);
        __syncthreads();
        if (tid < CCH)
            atomicAdd(&((float*)B)[hsh[2][tid]], xv * sg[2][tid]);
        __syncthreads();
        fft2048<false>(B, B + NHALF, tw, tid, NTHR);     // Z2 in B[0..2047]

        // ---- unpack F0,F1,F2 on half spectrum, products, accumulate
        for (int k = tid; k < NSPEC; k += NTHR) {
            float2 Zk = A[k];
            float2 Zm = A[(NFFT - k) & (NFFT - 1)];
            float2 F0 = make_float2(0.5f * (Zk.x + Zm.x), 0.5f * (Zk.y - Zm.y));
            float2 t1 = make_float2(Zk.x - Zm.x, Zk.y + Zm.y);   // Z - conj(Zm)
            float2 F1 = make_float2(0.5f * t1.y, -0.5f * t1.x);  // = t1/(2i)

            int j = k & (NHALF - 1);
            float2 Gk = B[j];
            float2 Gm = B[(NHALF - j) & (NHALF - 1)];
            float2 E  = make_float2(0.5f * (Gk.x + Gm.x), 0.5f * (Gk.y - Gm.y));
            float2 t2 = make_float2(Gk.x - Gm.x, Gk.y + Gm.y);
            float2 O  = make_float2(0.5f * t2.y, -0.5f * t2.x);
            float2 w  = tw[k];                                   // e^{-2pi i k/4096}
            float2 F2 = make_float2(E.x + w.x * O.x - w.y * O.y,
                                    E.y + w.x * O.y + w.y * O.x);

            float2 P2 = cmul(F0, F1);
            ac2[k].x += P2.x; ac2[k].y += P2.y;
            float2 P3 = cmul(P2, F2);
            ac3[k].x += P3.x; ac3[k].y += P3.y;
        }
        __syncthreads();
    }

    // flush per-CTA accumulators to the per-batch global half-spectrum accumulators
    for (int i = tid; i < NSPEC; i += NTHR) {
        atomicAdd(&g_acc2[b][i].x, ac2[i].x);
        atomicAdd(&g_acc2[b][i].y, ac2[i].y);
        atomicAdd(&g_acc3[b][i].x, ac3[i].x);
        atomicAdd(&g_acc3[b][i].y, ac3[i].y);
    }
}

__global__ void __launch_bounds__(NTHF, 1)
finalize_kernel(const float* __restrict__ alpha, float* __restrict__ out)
{
    extern __shared__ float2 smem[];
    float2* tw  = smem;
    float2* A   = smem + NFFT;
    float2* B   = smem + 2 * NFFT;
    float*  phi = (float*)(smem + 3 * NFFT);   // 8712 floats
    __shared__ float red[17];

    int tid = threadIdx.x;
    int b   = blockIdx.x;

    for (int j = tid; j < NFFT; j += NTHF) {
        float sn, cs;
        sincospif(-(float)j * (1.0f / 2048.0f), &sn, &cs);
        tw[j] = make_float2(cs, sn);
    }
    __syncthreads();

    const float inv_n = 1.0f / ((float)NPIX * (float)NFFT); // ifft 1/N and pixel mean

    // order-2 term: rebuild full Hermitian spectrum, inverse FFT
    for (int i = tid; i < NFFT; i += NTHF) {
        if (i <= NHALF) A[i] = g_acc2[b][i];
        else { float2 v = g_acc2[b][NFFT - i]; A[i] = make_float2(v.x, -v.y); }
    }
    __syncthreads();
    fft4096<true>(A, B, A, tw, tid, NTHF);
    {
        float a2 = alpha[2] * inv_n;
        for (int i = tid; i < NFFT; i += NTHF) phi[513 + i] = A[i].x * a2;
    }

    // order-3 term
    for (int i = tid; i < NFFT; i += NTHF) {
        if (i <= NHALF) A[i] = g_acc3[b][i];
        else { float2 v = g_acc3[b][NFFT - i]; A[i] = make_float2(v.x, -v.y); }
    }
    __syncthreads();
    fft4096<true>(A, B, A, tw, tid, NTHF);
    {
        float a3 = alpha[3] * inv_n;
        for (int i = tid; i < NFFT; i += NTHF) phi[513 + NFFT + i] = A[i].x * a3;
    }

    if (tid == 0) phi[0] = alpha[0];
    phi[1 + tid] = alpha[1] * g_first[b][tid] * (1.0f / (float)NPIX);
    __syncthreads();

    // signed sqrt (sign(0)=0 like jnp.sign) + norm reduction
    float lsum = 0.f;
    for (int i = tid; i < DOUT; i += NTHF) {
        float v = phi[i];
        float r;
        if (v > 0.f)      r =  sqrtf(v + 1e-12f);
        else if (v < 0.f) r = -sqrtf(-v + 1e-12f);
        else              r = 0.f;
        phi[i] = r;
        lsum += r * r;
    }
    #pragma unroll
    for (int off = 16; off > 0; off >>= 1)
        lsum += __shfl_down_sync(0xffffffffu, lsum, off);
    if ((tid & 31) == 0) red[tid >> 5] = lsum;
    __syncthreads();
    if (tid == 0) {
        float s = 0.f;
        #pragma unroll
        for (int k = 0; k < 16; k++) s += red[k];
        red[16] = 1.0f / sqrtf(s);
    }
    __syncthreads();
    float rn = red[16];
    for (int i = tid; i < DOUT; i += NTHF)
        out[(size_t)b * DOUT + i] = phi[i] * rn;
}

extern "C" void kernel_launch(void* const* d_in, const int* in_sizes, int n_in,
                              void* d_out, int out_size)
{
    const float* x     = (const float*)d_in[0];
    const float* alpha = (const float*)d_in[1];
    const int*   h     = (const int*)d_in[2];
    const int*   sb    = (const int*)d_in[3];
    float*       out   = (float*)d_out;

    const int MAIN_SMEM = (3 * NFFT + 2 * NSPEC) * (int)sizeof(float2); // 131088
    const int FIN_SMEM  = 3 * NFFT * (int)sizeof(float2) + 8712 * 4;    // 133152

    cudaFuncSetAttribute(poly_sketch_kernel,
                         cudaFuncAttributeMaxDynamicSharedMemorySize, MAIN_SMEM);
    cudaFuncSetAttribute(finalize_kernel,
                         cudaFuncAttributeMaxDynamicSharedMemorySize, FIN_SMEM);

    zero_kernel<<<(NB * NSPEC * 2 + 255) / 256, 256>>>();
    first_kernel<<<NB, CCH>>>(x);
    poly_sketch_kernel<<<NB * SLOTS, NTHR, MAIN_SMEM>>>(x, h, sb);
    finalize_kernel<<<NB, NTHF, FIN_SMEM>>>(alpha, out);
}

// round 3
// speedup vs baseline: 2.2706x; 1.3399x over previous
#include <cuda_runtime.h>
#include <math.h>

#define NFFT   4096
#define NHALF  2048
#define NSPEC  2049
#define CCH    512
#define NPIX   784
#define NB     8
#define SLOTS  18
#define DOUT   8705
#define NTHR   512

#define APAD   4224     // 4096 + 4096/32 padding
#define CPAD   2112     // 2048 + 64
#define SWI(i) ((i) + ((i) >> 5))

__device__ float2 g_acc2[NB][NSPEC];
__device__ float2 g_acc3[NB][NSPEC];
__device__ float  g_first[NB][CCH];

__device__ __forceinline__ float2 cmul(float2 a, float2 b) {
    return make_float2(a.x * b.x - a.y * b.y, a.x * b.y + a.y * b.x);
}

// ---------------- Stockham radix-8 stage (swizzled smem) ----------------
// sh = 12 - log2(n). Loads x_r = src[t + r*eighth]; stores dst[q + 8ps + m*s].
template<bool INV>
__device__ __forceinline__ void stage8(const float2* __restrict__ src,
                                       float2* __restrict__ dst,
                                       const float2* __restrict__ tw,
                                       int sh, int ls, int eighth,
                                       int tid, int nt)
{
    const float CC = 0.70710678118654752f;
    for (int t = tid; t < eighth; t += nt) {
        int p = t >> ls;
        int q = t & ((1 << ls) - 1);
        float2 x0 = src[SWI(t)];
        float2 x1 = src[SWI(t + eighth)];
        float2 x2 = src[SWI(t + 2 * eighth)];
        float2 x3 = src[SWI(t + 3 * eighth)];
        float2 x4 = src[SWI(t + 4 * eighth)];
        float2 x5 = src[SWI(t + 5 * eighth)];
        float2 x6 = src[SWI(t + 6 * eighth)];
        float2 x7 = src[SWI(t + 7 * eighth)];

        // even DFT4 over (x0,x2,x4,x6)
        float2 u0 = {x0.x + x4.x, x0.y + x4.y};
        float2 u1 = {x0.x - x4.x, x0.y - x4.y};
        float2 u2 = {x2.x + x6.x, x2.y + x6.y};
        float2 u3 = {x2.x - x6.x, x2.y - x6.y};
        float2 e0 = {u0.x + u2.x, u0.y + u2.y};
        float2 e2 = {u0.x - u2.x, u0.y - u2.y};
        float2 j3 = {-u3.y, u3.x};
        float2 e1, e3;
        if (!INV) { e1 = {u1.x - j3.x, u1.y - j3.y}; e3 = {u1.x + j3.x, u1.y + j3.y}; }
        else      { e1 = {u1.x + j3.x, u1.y + j3.y}; e3 = {u1.x - j3.x, u1.y - j3.y}; }

        // odd DFT4 over (x1,x3,x5,x7)
        float2 v0 = {x1.x + x5.x, x1.y + x5.y};
        float2 v1 = {x1.x - x5.x, x1.y - x5.y};
        float2 v2 = {x3.x + x7.x, x3.y + x7.y};
        float2 v3 = {x3.x - x7.x, x3.y - x7.y};
        float2 o0 = {v0.x + v2.x, v0.y + v2.y};
        float2 o2 = {v0.x - v2.x, v0.y - v2.y};
        float2 k3 = {-v3.y, v3.x};
        float2 o1, o3;
        if (!INV) { o1 = {v1.x - k3.x, v1.y - k3.y}; o3 = {v1.x + k3.x, v1.y + k3.y}; }
        else      { o1 = {v1.x + k3.x, v1.y + k3.y}; o3 = {v1.x - k3.x, v1.y - k3.y}; }

        // t_m = W8^{+-m} * o_m
        float2 t1, t2, t3;
        if (!INV) {
            t1 = { CC * (o1.x + o1.y),  CC * (o1.y - o1.x) };
            t2 = { o2.y, -o2.x };
            t3 = { CC * (o3.y - o3.x), -CC * (o3.x + o3.y) };
        } else {
            t1 = { CC * (o1.x - o1.y),  CC * (o1.y + o1.x) };
            t2 = { -o2.y, o2.x };
            t3 = { -CC * (o3.x + o3.y), CC * (o3.x - o3.y) };
        }
        float2 y0 = {e0.x + o0.x, e0.y + o0.y};
        float2 y4 = {e0.x - o0.x, e0.y - o0.y};
        float2 y1 = {e1.x + t1.x, e1.y + t1.y};
        float2 y5 = {e1.x - t1.x, e1.y - t1.y};
        float2 y2 = {e2.x + t2.x, e2.y + t2.y};
        float2 y6 = {e2.x - t2.x, e2.y - t2.y};
        float2 y3 = {e3.x + t3.x, e3.y + t3.y};
        float2 y7 = {e3.x - t3.x, e3.y - t3.y};

        float2 w1 = tw[p << sh];
        float2 w2 = tw[(2 * p) << sh];
        float2 w4 = tw[(4 * p) << sh];
        if (INV) { w1.y = -w1.y; w2.y = -w2.y; w4.y = -w4.y; }
        float2 w3 = cmul(w1, w2);
        float2 w5 = cmul(w1, w4);
        float2 w6 = cmul(w2, w4);
        float2 w7 = cmul(w3, w4);
        y1 = cmul(y1, w1); y2 = cmul(y2, w2); y3 = cmul(y3, w3);
        y4 = cmul(y4, w4); y5 = cmul(y5, w5); y6 = cmul(y6, w6); y7 = cmul(y7, w7);

        int s = 1 << ls;
        int o = q + (p << (ls + 3));
        dst[SWI(o)]         = y0;
        dst[SWI(o + s)]     = y1;
        dst[SWI(o + 2*s)]   = y2;
        dst[SWI(o + 3*s)]   = y3;
        dst[SWI(o + 4*s)]   = y4;
        dst[SWI(o + 5*s)]   = y5;
        dst[SWI(o + 6*s)]   = y6;
        dst[SWI(o + 7*s)]   = y7;
    }
}

// ---------------- Stockham radix-4 stage (tail of 2048 FFT) ----------------
template<bool INV>
__device__ __forceinline__ void stage4(const float2* __restrict__ src,
                                       float2* __restrict__ dst,
                                       const float2* __restrict__ tw,
                                       int sh, int ls, int quarter,
                                       int tid, int nt)
{
    for (int t = tid; t < quarter; t += nt) {
        int p = t >> ls;
        int q = t & ((1 << ls) - 1);
        float2 a = src[SWI(t)];
        float2 b = src[SWI(t + quarter)];
        float2 c = src[SWI(t + 2 * quarter)];
        float2 d = src[SWI(t + 3 * quarter)];
        float2 apc  = {a.x + c.x, a.y + c.y};
        float2 amc  = {a.x - c.x, a.y - c.y};
        float2 bpd  = {b.x + d.x, b.y + d.y};
        float2 jbmd = {-(b.y - d.y), b.x - d.x};
        float2 y0 = {apc.x + bpd.x, apc.y + bpd.y};
        float2 y2 = {apc.x - bpd.x, apc.y - bpd.y};
        float2 y1, y3;
        if (!INV) { y1 = {amc.x - jbmd.x, amc.y - jbmd.y}; y3 = {amc.x + jbmd.x, amc.y + jbmd.y}; }
        else      { y1 = {amc.x + jbmd.x, amc.y + jbmd.y}; y3 = {amc.x - jbmd.x, amc.y - jbmd.y}; }
        int ti = p << sh;
        float2 w1 = tw[ti], w2 = tw[2 * ti], w3 = tw[3 * ti];
        if (INV) { w1.y = -w1.y; w2.y = -w2.y; w3.y = -w3.y; }
        y1 = cmul(y1, w1);
        y2 = cmul(y2, w2);
        y3 = cmul(y3, w3);
        int s = 1 << ls;
        int o = q + (p << (ls + 2));
        dst[SWI(o)]       = y0;
        dst[SWI(o + s)]   = y1;
        dst[SWI(o + 2*s)] = y2;
        dst[SWI(o + 3*s)] = y3;
    }
}

// 4096-pt FFT, 4 radix-8 stages, in-place over A (B scratch).
template<bool INV>
__device__ void fft4096_r8(float2* A, float2* B, const float2* tw, int tid, int nt)
{
    stage8<INV>(A, B, tw, 0, 0, 512, tid, nt); __syncthreads();
    stage8<INV>(B, A, tw, 3, 3, 512, tid, nt); __syncthreads();
    stage8<INV>(A, B, tw, 6, 6, 512, tid, nt); __syncthreads();
    stage8<INV>(B, A, tw, 9, 9, 512, tid, nt); __syncthreads();
}

// 2048-pt FFT, 3 radix-8 + 1 radix-4 stage, in-place over C (D scratch).
template<bool INV>
__device__ void fft2048_r8(float2* C, float2* D, const float2* tw, int tid, int nt)
{
    stage8<INV>(C, D, tw, 1, 0, 256, tid, nt); __syncthreads();
    stage8<INV>(D, C, tw, 4, 3, 256, tid, nt); __syncthreads();
    stage8<INV>(C, D, tw, 7, 6, 256, tid, nt); __syncthreads();
    stage4<INV>(D, C, tw, 10, 9, 512, tid, nt); __syncthreads();
}

__device__ __forceinline__ void binprod(float2 Zk, float2 Zm, float2 Gk, float2 Gm,
                                        float2 w, float2& P2, float2& P3)
{
    float2 F0 = { 0.5f * (Zk.x + Zm.x),  0.5f * (Zk.y - Zm.y) };
    float2 F1 = { 0.5f * (Zk.y + Zm.y), -0.5f * (Zk.x - Zm.x) };
    float2 E  = { 0.5f * (Gk.x + Gm.x),  0.5f * (Gk.y - Gm.y) };
    float2 O  = { 0.5f * (Gk.y + Gm.y), -0.5f * (Gk.x - Gm.x) };
    float2 F2 = { E.x + w.x * O.x - w.y * O.y, E.y + w.x * O.y + w.y * O.x };
    P2 = cmul(F0, F1);
    P3 = cmul(P2, F2);
}

__global__ void zero_kernel()
{
    int i = blockIdx.x * blockDim.x + threadIdx.x;
    int n = NB * NSPEC * 2;
    if (i < n) {
        ((float*)g_acc2)[i] = 0.f;
        ((float*)g_acc3)[i] = 0.f;
    }
}

__global__ void first_kernel(const float* __restrict__ x)
{
    int b = blockIdx.x;
    int c = threadIdx.x;
    const float* p = x + (size_t)b * NPIX * CCH + c;
    float s = 0.f;
    #pragma unroll 8
    for (int i = 0; i < NPIX; i++) s += p[(size_t)i * CCH];
    g_first[b][c] = s;
}

__global__ void __launch_bounds__(NTHR, 1)
poly_sketch_kernel(const float* __restrict__ x,
                   const int* __restrict__ h_idx,
                   const int* __restrict__ s_bits)
{
    extern __shared__ float2 smem[];
    float2* tw = smem;                  // 4096
    float2* A  = smem + 4096;           // APAD
    float2* B  = A + APAD;              // APAD
    float2* Cc = B + APAD;              // CPAD
    float2* D  = Cc + CPAD;             // CPAD
    __shared__ int   hsh[3][CCH];
    __shared__ float sg[3][CCH];

    int tid  = threadIdx.x;
    int b    = blockIdx.x / SLOTS;
    int slot = blockIdx.x % SLOTS;

    for (int j = tid; j < NFFT; j += NTHR) {
        float sn, cs;
        sincospif(-(float)j * (1.0f / 2048.0f), &sn, &cs);
        tw[j] = make_float2(cs, sn);
    }
    for (int j = tid; j < APAD; j += NTHR) A[j] = make_float2(0.f, 0.f);
    for (int j = tid; j < CPAD; j += NTHR) Cc[j] = make_float2(0.f, 0.f);
    #pragma unroll
    for (int t = 0; t < 3; t++) {
        hsh[t][tid] = h_idx[t * CCH + tid];
        sg[t][tid]  = (float)(2 * s_bits[t * CCH + tid] - 1);
    }
    __syncthreads();

    float2 a2[5], a3[5];
    #pragma unroll
    for (int i = 0; i < 5; i++) { a2[i] = make_float2(0.f, 0.f); a3[i] = make_float2(0.f, 0.f); }

    int h0 = hsh[0][tid], h1 = hsh[1][tid], h2 = hsh[2][tid];
    float s0 = sg[0][tid], s1 = sg[1][tid], s2 = sg[2][tid];
    int cfa = 2 * SWI(h2 >> 1) + (h2 & 1);      // swizzled float index into Cc

    for (int pix = slot; pix < NPIX; pix += SLOTS) {
        float xv = x[((size_t)(b * NPIX + pix)) * CCH + tid];

        // scatter: s0 -> A.x, s1 -> A.y (4096 bins); s2 packed even+i*odd in Cc (2048)
        atomicAdd(&A[SWI(h0)].x, xv * s0);
        atomicAdd(&A[SWI(h1)].y, xv * s1);
        atomicAdd(&((float*)Cc)[cfa], xv * s2);
        __syncthreads();

        fft4096_r8<false>(A, B, tw, tid, NTHR);    // Z in A
        fft2048_r8<false>(Cc, D, tw, tid, NTHR);   // G in Cc

        // unpack bins in (k, 2048-k) pairs; accumulate into regs; zero A/Cc in-pass.
        // All locations read/zeroed by a pair are exclusively owned by this thread.
        #pragma unroll
        for (int jj = 0; jj < 2; jj++) {
            int k  = tid + jj * 512;               // 0..1023
            int km = (NFFT - k) & (NFFT - 1);      // 4096-k (k=0 -> 0)
            int kb = 2048 - k;                     // partner bin 1025..2048
            int jm = (NHALF - k) & (NHALF - 1);    // 2048-k mod 2048 (k=0 -> 0)
            float2 Zk  = A[SWI(k)];
            float2 Zm  = A[SWI(km)];
            float2 Zk2 = A[SWI(kb)];
            float2 Zm2 = A[SWI(2048 + k)];
            float2 Gk  = Cc[SWI(k)];
            float2 Gm  = Cc[SWI(jm)];
            float2 w   = tw[k];
            float2 P2a, P3a, P2b, P3b;
            binprod(Zk,  Zm,  Gk, Gm, w, P2a, P3a);
            binprod(Zk2, Zm2, Gm, Gk, make_float2(-w.x, w.y), P2b, P3b);
            a2[2*jj].x   += P2a.x; a2[2*jj].y   += P2a.y;
            a3[2*jj].x   += P3a.x; a3[2*jj].y   += P3a.y;
            a2[2*jj+1].x += P2b.x; a2[2*jj+1].y += P2b.y;
            a3[2*jj+1].x += P3b.x; a3[2*jj+1].y += P3b.y;
            float2 z = make_float2(0.f, 0.f);
            A[SWI(k)] = z; A[SWI(km)] = z; A[SWI(kb)] = z; A[SWI(2048 + k)] = z;
            Cc[SWI(k)] = z; Cc[SWI(jm)] = z;
        }
        if (tid == 0) {                            // middle bin 1024 (self-paired)
            float2 Zk = A[SWI(1024)], Zm = A[SWI(3072)];
            float2 Gk = Cc[SWI(1024)];
            float2 P2e, P3e;
            binprod(Zk, Zm, Gk, Gk, tw[1024], P2e, P3e);
            a2[4].x += P2e.x; a2[4].y += P2e.y;
            a3[4].x += P3e.x; a3[4].y += P3e.y;
            float2 z = make_float2(0.f, 0.f);
            A[SWI(1024)] = z; A[SWI(3072)] = z; Cc[SWI(1024)] = z;
        }
        __syncthreads();
    }

    // flush register accumulators to per-batch global half-spectrum accumulators
    int bins[4] = { tid, 2048 - tid, tid + 512, 1536 - tid };
    #pragma unroll
    for (int i = 0; i < 4; i++) {
        atomicAdd(&g_acc2[b][bins[i]].x, a2[i].x);
        atomicAdd(&g_acc2[b][bins[i]].y, a2[i].y);
        atomicAdd(&g_acc3[b][bins[i]].x, a3[i].x);
        atomicAdd(&g_acc3[b][bins[i]].y, a3[i].y);
    }
    if (tid == 0) {
        atomicAdd(&g_acc2[b][1024].x, a2[4].x);
        atomicAdd(&g_acc2[b][1024].y, a2[4].y);
        atomicAdd(&g_acc3[b][1024].x, a3[4].x);
        atomicAdd(&g_acc3[b][1024].y, a3[4].y);
    }
}

__global__ void __launch_bounds__(NTHR, 1)
finalize_kernel(const float* __restrict__ alpha, float* __restrict__ out)
{
    extern __shared__ float2 smem[];
    float2* tw  = smem;
    float2* A   = smem + 4096;
    float2* B   = A + APAD;
    float*  phi = (float*)(B + APAD);          // 8712 floats
    __shared__ float red[17];

    int tid = threadIdx.x;
    int b   = blockIdx.x;

    for (int j = tid; j < NFFT; j += NTHR) {
        float sn, cs;
        sincospif(-(float)j * (1.0f / 2048.0f), &sn, &cs);
        tw[j] = make_float2(cs, sn);
    }
    __syncthreads();

    const float inv_n = 1.0f / ((float)NPIX * (float)NFFT);

    for (int i = tid; i < NFFT; i += NTHR) {
        if (i <= NHALF) A[SWI(i)] = g_acc2[b][i];
        else { float2 v = g_acc2[b][NFFT - i]; A[SWI(i)] = make_float2(v.x, -v.y); }
    }
    __syncthreads();
    fft4096_r8<true>(A, B, tw, tid, NTHR);
    {
        float a2c = alpha[2] * inv_n;
        for (int i = tid; i < NFFT; i += NTHR) phi[513 + i] = A[SWI(i)].x * a2c;
    }
    __syncthreads();

    for (int i = tid; i < NFFT; i += NTHR) {
        if (i <= NHALF) A[SWI(i)] = g_acc3[b][i];
        else { float2 v = g_acc3[b][NFFT - i]; A[SWI(i)] = make_float2(v.x, -v.y); }
    }
    __syncthreads();
    fft4096_r8<true>(A, B, tw, tid, NTHR);
    {
        float a3c = alpha[3] * inv_n;
        for (int i = tid; i < NFFT; i += NTHR) phi[513 + NFFT + i] = A[SWI(i)].x * a3c;
    }

    if (tid == 0) phi[0] = alpha[0];
    phi[1 + tid] = alpha[1] * g_first[b][tid] * (1.0f / (float)NPIX);
    __syncthreads();

    float lsum = 0.f;
    for (int i = tid; i < DOUT; i += NTHR) {
        float v = phi[i];
        float r;
        if (v > 0.f)      r =  sqrtf(v + 1e-12f);
        else if (v < 0.f) r = -sqrtf(-v + 1e-12f);
        else              r = 0.f;
        phi[i] = r;
        lsum += r * r;
    }
    #pragma unroll
    for (int off = 16; off > 0; off >>= 1)
        lsum += __shfl_down_sync(0xffffffffu, lsum, off);
    if ((tid & 31) == 0) red[tid >> 5] = lsum;
    __syncthreads();
    if (tid == 0) {
        float s = 0.f;
        #pragma unroll
        for (int k = 0; k < 16; k++) s += red[k];
        red[16] = 1.0f / sqrtf(s);
    }
    __syncthreads();
    float rn = red[16];
    for (int i = tid; i < DOUT; i += NTHR)
        out[(size_t)b * DOUT + i] = phi[i] * rn;
}

extern "C" void kernel_launch(void* const* d_in, const int* in_sizes, int n_in,
                              void* d_out, int out_size)
{
    const float* x     = (const float*)d_in[0];
    const float* alpha = (const float*)d_in[1];
    const int*   h     = (const int*)d_in[2];
    const int*   sb    = (const int*)d_in[3];
    float*       out   = (float*)d_out;

    const int MAIN_SMEM = (4096 + 2 * APAD + 2 * CPAD) * (int)sizeof(float2); // 134144
    const int FIN_SMEM  = (4096 + 2 * APAD) * (int)sizeof(float2) + 8712 * 4; // 135200

    cudaFuncSetAttribute(poly_sketch_kernel,
                         cudaFuncAttributeMaxDynamicSharedMemorySize, MAIN_SMEM);
    cudaFuncSetAttribute(finalize_kernel,
                         cudaFuncAttributeMaxDynamicSharedMemorySize, FIN_SMEM);

    zero_kernel<<<(NB * NSPEC * 2 + 255) / 256, 256>>>();
    first_kernel<<<NB, CCH>>>(x);
    poly_sketch_kernel<<<NB * SLOTS, NTHR, MAIN_SMEM>>>(x, h, sb);
    finalize_kernel<<<NB, NTHR, FIN_SMEM>>>(alpha, out);
}

// round 4
// speedup vs baseline: 2.3834x; 1.0497x over previous
#include <cuda_runtime.h>
#include <math.h>

#define NFFT   4096
#define NHALF  2048
#define NSPEC  2049
#define CCH    512
#define NPIX   784
#define NB     8
#define SLOTS  18
#define DOUT   8705
#define NTHR   512

#define NTW    2048     // twiddle table entries (all stage indices < 2048)
#define APAD   4224     // 4096 + 4096/32 padding
#define CPAD   2112     // 2048 + 64
#define SWI(i) ((i) + ((i) >> 5))

__device__ float2 g_acc2[NB][NSPEC];
__device__ float2 g_acc3[NB][NSPEC];
__device__ float  g_first[NB][CCH];

__device__ __forceinline__ float2 cmul(float2 a, float2 b) {
    return make_float2(a.x * b.x - a.y * b.y, a.x * b.y + a.y * b.x);
}

// ---------------- Stockham radix-8 stage (swizzled smem) ----------------
template<bool INV>
__device__ __forceinline__ void stage8(const float2* __restrict__ src,
                                       float2* __restrict__ dst,
                                       const float2* __restrict__ tw,
                                       int sh, int ls, int eighth,
                                       int tid, int nt)
{
    const float CC = 0.70710678118654752f;
    for (int t = tid; t < eighth; t += nt) {
        int p = t >> ls;
        int q = t & ((1 << ls) - 1);
        float2 x0 = src[SWI(t)];
        float2 x1 = src[SWI(t + eighth)];
        float2 x2 = src[SWI(t + 2 * eighth)];
        float2 x3 = src[SWI(t + 3 * eighth)];
        float2 x4 = src[SWI(t + 4 * eighth)];
        float2 x5 = src[SWI(t + 5 * eighth)];
        float2 x6 = src[SWI(t + 6 * eighth)];
        float2 x7 = src[SWI(t + 7 * eighth)];

        float2 u0 = {x0.x + x4.x, x0.y + x4.y};
        float2 u1 = {x0.x - x4.x, x0.y - x4.y};
        float2 u2 = {x2.x + x6.x, x2.y + x6.y};
        float2 u3 = {x2.x - x6.x, x2.y - x6.y};
        float2 e0 = {u0.x + u2.x, u0.y + u2.y};
        float2 e2 = {u0.x - u2.x, u0.y - u2.y};
        float2 j3 = {-u3.y, u3.x};
        float2 e1, e3;
        if (!INV) { e1 = {u1.x - j3.x, u1.y - j3.y}; e3 = {u1.x + j3.x, u1.y + j3.y}; }
        else      { e1 = {u1.x + j3.x, u1.y + j3.y}; e3 = {u1.x - j3.x, u1.y - j3.y}; }

        float2 v0 = {x1.x + x5.x, x1.y + x5.y};
        float2 v1 = {x1.x - x5.x, x1.y - x5.y};
        float2 v2 = {x3.x + x7.x, x3.y + x7.y};
        float2 v3 = {x3.x - x7.x, x3.y - x7.y};
        float2 o0 = {v0.x + v2.x, v0.y + v2.y};
        float2 o2 = {v0.x - v2.x, v0.y - v2.y};
        float2 k3 = {-v3.y, v3.x};
        float2 o1, o3;
        if (!INV) { o1 = {v1.x - k3.x, v1.y - k3.y}; o3 = {v1.x + k3.x, v1.y + k3.y}; }
        else      { o1 = {v1.x + k3.x, v1.y + k3.y}; o3 = {v1.x - k3.x, v1.y - k3.y}; }

        float2 t1, t2, t3;
        if (!INV) {
            t1 = { CC * (o1.x + o1.y),  CC * (o1.y - o1.x) };
            t2 = { o2.y, -o2.x };
            t3 = { CC * (o3.y - o3.x), -CC * (o3.x + o3.y) };
        } else {
            t1 = { CC * (o1.x - o1.y),  CC * (o1.y + o1.x) };
            t2 = { -o2.y, o2.x };
            t3 = { -CC * (o3.x + o3.y), CC * (o3.x - o3.y) };
        }
        float2 y0 = {e0.x + o0.x, e0.y + o0.y};
        float2 y4 = {e0.x - o0.x, e0.y - o0.y};
        float2 y1 = {e1.x + t1.x, e1.y + t1.y};
        float2 y5 = {e1.x - t1.x, e1.y - t1.y};
        float2 y2 = {e2.x + t2.x, e2.y + t2.y};
        float2 y6 = {e2.x - t2.x, e2.y - t2.y};
        float2 y3 = {e3.x + t3.x, e3.y + t3.y};
        float2 y7 = {e3.x - t3.x, e3.y - t3.y};

        float2 w1 = tw[p << sh];
        float2 w2 = tw[(2 * p) << sh];
        float2 w4 = tw[(4 * p) << sh];
        if (INV) { w1.y = -w1.y; w2.y = -w2.y; w4.y = -w4.y; }
        float2 w3 = cmul(w1, w2);
        float2 w5 = cmul(w1, w4);
        float2 w6 = cmul(w2, w4);
        float2 w7 = cmul(w3, w4);
        y1 = cmul(y1, w1); y2 = cmul(y2, w2); y3 = cmul(y3, w3);
        y4 = cmul(y4, w4); y5 = cmul(y5, w5); y6 = cmul(y6, w6); y7 = cmul(y7, w7);

        int s = 1 << ls;
        int o = q + (p << (ls + 3));
        dst[SWI(o)]         = y0;
        dst[SWI(o + s)]     = y1;
        dst[SWI(o + 2*s)]   = y2;
        dst[SWI(o + 3*s)]   = y3;
        dst[SWI(o + 4*s)]   = y4;
        dst[SWI(o + 5*s)]   = y5;
        dst[SWI(o + 6*s)]   = y6;
        dst[SWI(o + 7*s)]   = y7;
    }
}

// ---------------- radix-4 tail stage (p==0 region still uses tw, idx<2048) ----
template<bool INV>
__device__ __forceinline__ void stage4(const float2* __restrict__ src,
                                       float2* __restrict__ dst,
                                       const float2* __restrict__ tw,
                                       int sh, int ls, int quarter,
                                       int tid, int nt)
{
    for (int t = tid; t < quarter; t += nt) {
        int p = t >> ls;
        int q = t & ((1 << ls) - 1);
        float2 a = src[SWI(t)];
        float2 b = src[SWI(t + quarter)];
        float2 c = src[SWI(t + 2 * quarter)];
        float2 d = src[SWI(t + 3 * quarter)];
        float2 apc  = {a.x + c.x, a.y + c.y};
        float2 amc  = {a.x - c.x, a.y - c.y};
        float2 bpd  = {b.x + d.x, b.y + d.y};
        float2 jbmd = {-(b.y - d.y), b.x - d.x};
        float2 y0 = {apc.x + bpd.x, apc.y + bpd.y};
        float2 y2 = {apc.x - bpd.x, apc.y - bpd.y};
        float2 y1, y3;
        if (!INV) { y1 = {amc.x - jbmd.x, amc.y - jbmd.y}; y3 = {amc.x + jbmd.x, amc.y + jbmd.y}; }
        else      { y1 = {amc.x + jbmd.x, amc.y + jbmd.y}; y3 = {amc.x - jbmd.x, amc.y - jbmd.y}; }
        int ti = p << sh;
        float2 w1 = tw[ti], w2 = tw[2 * ti], w3 = cmul(w1, w2);
        if (INV) { w1.y = -w1.y; w2.y = -w2.y; w3.y = -w3.y; }
        y1 = cmul(y1, w1);
        y2 = cmul(y2, w2);
        y3 = cmul(y3, w3);
        int s = 1 << ls;
        int o = q + (p << (ls + 2));
        dst[SWI(o)]       = y0;
        dst[SWI(o + s)]   = y1;
        dst[SWI(o + 2*s)] = y2;
        dst[SWI(o + 3*s)] = y3;
    }
}

// 4096-pt FFT, 4 radix-8 stages, in-place over A (B scratch). (finalize path)
template<bool INV>
__device__ void fft4096_r8(float2* A, float2* B, const float2* tw, int tid, int nt)
{
    stage8<INV>(A, B, tw, 0, 0, 512, tid, nt); __syncthreads();
    stage8<INV>(B, A, tw, 3, 3, 512, tid, nt); __syncthreads();
    stage8<INV>(A, B, tw, 6, 6, 512, tid, nt); __syncthreads();
    stage8<INV>(B, A, tw, 9, 9, 512, tid, nt); __syncthreads();
}

__device__ __forceinline__ void binprod(float2 Zk, float2 Zm, float2 Gk, float2 Gm,
                                        float2 w, float2& P2, float2& P3)
{
    float2 F0 = { 0.5f * (Zk.x + Zm.x),  0.5f * (Zk.y - Zm.y) };
    float2 F1 = { 0.5f * (Zk.y + Zm.y), -0.5f * (Zk.x - Zm.x) };
    float2 E  = { 0.5f * (Gk.x + Gm.x),  0.5f * (Gk.y - Gm.y) };
    float2 O  = { 0.5f * (Gk.y + Gm.y), -0.5f * (Gk.x - Gm.x) };
    float2 F2 = { E.x + w.x * O.x - w.y * O.y, E.y + w.x * O.y + w.y * O.x };
    P2 = cmul(F0, F1);
    P3 = cmul(P2, F2);
}

__global__ void zero_kernel()
{
    int i = blockIdx.x * blockDim.x + threadIdx.x;
    int n = NB * NSPEC * 2;
    if (i < n) {
        ((float*)g_acc2)[i] = 0.f;
        ((float*)g_acc3)[i] = 0.f;
    }
}

__global__ void first_kernel(const float* __restrict__ x)
{
    int b = blockIdx.x;
    int c = threadIdx.x;
    const float* p = x + (size_t)b * NPIX * CCH + c;
    float s = 0.f;
    #pragma unroll 8
    for (int i = 0; i < NPIX; i++) s += p[(size_t)i * CCH];
    g_first[b][c] = s;
}

__global__ void __launch_bounds__(NTHR, 1)
poly_sketch_kernel(const float* __restrict__ x,
                   const int* __restrict__ h_idx,
                   const int* __restrict__ s_bits)
{
    extern __shared__ float2 smem[];
    float2* tw = smem;                  // 2048
    float2* A  = smem + NTW;            // APAD
    float2* B  = A + APAD;              // APAD
    float2* Cc = B + APAD;              // CPAD
    float2* D  = Cc + CPAD;             // CPAD

    int tid  = threadIdx.x;
    int b    = blockIdx.x / SLOTS;
    int slot = blockIdx.x % SLOTS;

    for (int j = tid; j < NTW; j += NTHR) {
        float sn, cs;
        sincospif(-(float)j * (1.0f / 2048.0f), &sn, &cs);
        tw[j] = make_float2(cs, sn);
    }
    for (int j = tid; j < APAD; j += NTHR) A[j] = make_float2(0.f, 0.f);
    for (int j = tid; j < CPAD; j += NTHR) Cc[j] = make_float2(0.f, 0.f);

    // per-thread hash/sign straight into registers
    int   h0 = h_idx[tid],          h1 = h_idx[CCH + tid],        h2 = h_idx[2 * CCH + tid];
    float s0 = (float)(2 * s_bits[tid] - 1);
    float s1 = (float)(2 * s_bits[CCH + tid] - 1);
    float s2 = (float)(2 * s_bits[2 * CCH + tid] - 1);
    int cfa = 2 * SWI(h2 >> 1) + (h2 & 1);
    __syncthreads();

    float2 a2[5], a3[5];
    #pragma unroll
    for (int i = 0; i < 5; i++) { a2[i] = make_float2(0.f, 0.f); a3[i] = make_float2(0.f, 0.f); }

    for (int pix = slot; pix < NPIX; pix += SLOTS) {
        float xv = x[((size_t)(b * NPIX + pix)) * CCH + tid];

        atomicAdd(&A[SWI(h0)].x, xv * s0);
        atomicAdd(&A[SWI(h1)].y, xv * s1);
        atomicAdd(&((float*)Cc)[cfa], xv * s2);
        __syncthreads();

        // interleaved FFT phases: 4096-pt (A<->B) + 2048-pt (Cc<->D) per barrier
        stage8<false>(A, B, tw, 0, 0, 512, tid, NTHR);
        stage8<false>(Cc, D, tw, 1, 0, 256, tid, NTHR);
        __syncthreads();
        stage8<false>(B, A, tw, 3, 3, 512, tid, NTHR);
        stage8<false>(D, Cc, tw, 4, 3, 256, tid, NTHR);
        __syncthreads();
        stage8<false>(A, B, tw, 6, 6, 512, tid, NTHR);
        stage8<false>(Cc, D, tw, 7, 6, 256, tid, NTHR);
        __syncthreads();
        stage8<false>(B, A, tw, 9, 9, 512, tid, NTHR);
        stage4<false>(D, Cc, tw, 10, 9, 512, tid, NTHR);
        __syncthreads();
        // Z (s0+i*s1 spectrum) in A; G (s2 even/odd-packed spectrum) in Cc

        #pragma unroll
        for (int jj = 0; jj < 2; jj++) {
            int k  = tid + jj * 512;
            int km = (NFFT - k) & (NFFT - 1);
            int kb = 2048 - k;
            int jm = (NHALF - k) & (NHALF - 1);
            float2 Zk  = A[SWI(k)];
            float2 Zm  = A[SWI(km)];
            float2 Zk2 = A[SWI(kb)];
            float2 Zm2 = A[SWI(2048 + k)];
            float2 Gk  = Cc[SWI(k)];
            float2 Gm  = Cc[SWI(jm)];
            float2 w   = tw[k];
            float2 P2a, P3a, P2b, P3b;
            binprod(Zk,  Zm,  Gk, Gm, w, P2a, P3a);
            binprod(Zk2, Zm2, Gm, Gk, make_float2(-w.x, w.y), P2b, P3b);
            a2[2*jj].x   += P2a.x; a2[2*jj].y   += P2a.y;
            a3[2*jj].x   += P3a.x; a3[2*jj].y   += P3a.y;
            a2[2*jj+1].x += P2b.x; a2[2*jj+1].y += P2b.y;
            a3[2*jj+1].x += P3b.x; a3[2*jj+1].y += P3b.y;
            float2 z = make_float2(0.f, 0.f);
            A[SWI(k)] = z; A[SWI(km)] = z; A[SWI(kb)] = z; A[SWI(2048 + k)] = z;
            Cc[SWI(k)] = z; Cc[SWI(jm)] = z;
        }
        if (tid == 0) {
            float2 Zk = A[SWI(1024)], Zm = A[SWI(3072)];
            float2 Gk = Cc[SWI(1024)];
            float2 P2e, P3e;
            binprod(Zk, Zm, Gk, Gk, tw[1024], P2e, P3e);
            a2[4].x += P2e.x; a2[4].y += P2e.y;
            a3[4].x += P3e.x; a3[4].y += P3e.y;
            float2 z = make_float2(0.f, 0.f);
            A[SWI(1024)] = z; A[SWI(3072)] = z; Cc[SWI(1024)] = z;
        }
        __syncthreads();
    }

    int bins[4] = { tid, 2048 - tid, tid + 512, 1536 - tid };
    #pragma unroll
    for (int i = 0; i < 4; i++) {
        atomicAdd(&g_acc2[b][bins[i]].x, a2[i].x);
        atomicAdd(&g_acc2[b][bins[i]].y, a2[i].y);
        atomicAdd(&g_acc3[b][bins[i]].x, a3[i].x);
        atomicAdd(&g_acc3[b][bins[i]].y, a3[i].y);
    }
    if (tid == 0) {
        atomicAdd(&g_acc2[b][1024].x, a2[4].x);
        atomicAdd(&g_acc2[b][1024].y, a2[4].y);
        atomicAdd(&g_acc3[b][1024].x, a3[4].x);
        atomicAdd(&g_acc3[b][1024].y, a3[4].y);
    }
}

__global__ void __launch_bounds__(NTHR, 1)
finalize_kernel(const float* __restrict__ alpha, float* __restrict__ out)
{
    extern __shared__ float2 smem[];
    float2* tw  = smem;                 // 2048
    float2* A   = smem + NTW;
    float2* B   = A + APAD;
    float*  phi = (float*)(B + APAD);   // 8712 floats
    __shared__ float red[17];

    int tid = threadIdx.x;
    int b   = blockIdx.x;

    for (int j = tid; j < NTW; j += NTHR) {
        float sn, cs;
        sincospif(-(float)j * (1.0f / 2048.0f), &sn, &cs);
        tw[j] = make_float2(cs, sn);
    }
    __syncthreads();

    const float inv_n = 1.0f / ((float)NPIX * (float)NFFT);

    for (int i = tid; i < NFFT; i += NTHR) {
        if (i <= NHALF) A[SWI(i)] = g_acc2[b][i];
        else { float2 v = g_acc2[b][NFFT - i]; A[SWI(i)] = make_float2(v.x, -v.y); }
    }
    __syncthreads();
    fft4096_r8<true>(A, B, tw, tid, NTHR);
    {
        float a2c = alpha[2] * inv_n;
        for (int i = tid; i < NFFT; i += NTHR) phi[513 + i] = A[SWI(i)].x * a2c;
    }
    __syncthreads();

    for (int i = tid; i < NFFT; i += NTHR) {
        if (i <= NHALF) A[SWI(i)] = g_acc3[b][i];
        else { float2 v = g_acc3[b][NFFT - i]; A[SWI(i)] = make_float2(v.x, -v.y); }
    }
    __syncthreads();
    fft4096_r8<true>(A, B, tw, tid, NTHR);
    {
        float a3c = alpha[3] * inv_n;
        for (int i = tid; i < NFFT; i += NTHR) phi[513 + NFFT + i] = A[SWI(i)].x * a3c;
    }

    if (tid == 0) phi[0] = alpha[0];
    phi[1 + tid] = alpha[1] * g_first[b][tid] * (1.0f / (float)NPIX);
    __syncthreads();

    float lsum = 0.f;
    for (int i = tid; i < DOUT; i += NTHR) {
        float v = phi[i];
        float r;
        if (v > 0.f)      r =  sqrtf(v + 1e-12f);
        else if (v < 0.f) r = -sqrtf(-v + 1e-12f);
        else              r = 0.f;
        phi[i] = r;
        lsum += r * r;
    }
    #pragma unroll
    for (int off = 16; off > 0; off >>= 1)
        lsum += __shfl_down_sync(0xffffffffu, lsum, off);
    if ((tid & 31) == 0) red[tid >> 5] = lsum;
    __syncthreads();
    if (tid == 0) {
        float s = 0.f;
        #pragma unroll
        for (int k = 0; k < 16; k++) s += red[k];
        red[16] = 1.0f / sqrtf(s);
    }
    __syncthreads();
    float rn = red[16];
    for (int i = tid; i < DOUT; i += NTHR)
        out[(size_t)b * DOUT + i] = phi[i] * rn;
}

extern "C" void kernel_launch(void* const* d_in, const int* in_sizes, int n_in,
                              void* d_out, int out_size)
{
    const float* x     = (const float*)d_in[0];
    const float* alpha = (const float*)d_in[1];
    const int*   h     = (const int*)d_in[2];
    const int*   sb    = (const int*)d_in[3];
    float*       out   = (float*)d_out;

    const int MAIN_SMEM = (NTW + 2 * APAD + 2 * CPAD) * (int)sizeof(float2); // 117760
    const int FIN_SMEM  = (NTW + 2 * APAD) * (int)sizeof(float2) + 8712 * 4; // 118816

    cudaFuncSetAttribute(poly_sketch_kernel,
                         cudaFuncAttributeMaxDynamicSharedMemorySize, MAIN_SMEM);
    cudaFuncSetAttribute(finalize_kernel,
                         cudaFuncAttributeMaxDynamicSharedMemorySize, FIN_SMEM);

    zero_kernel<<<(NB * NSPEC * 2 + 255) / 256, 256>>>();
    first_kernel<<<NB, CCH>>>(x);
    poly_sketch_kernel<<<NB * SLOTS, NTHR, MAIN_SMEM>>>(x, h, sb);
    finalize_kernel<<<NB, NTHR, FIN_SMEM>>>(alpha, out);
}